// round 2
// baseline (speedup 1.0000x reference)
#include <cuda_runtime.h>
#include <math.h>

#define F_INF __int_as_float(0x7f800000)

// Problem dims
#define Dm 768
#define Em 768
#define Hh 12
#define Bb 4
#define Ss 512
#define Vv 32000
#define Tt (Bb*Ss)   // 2048

// ---------------- scratch (device globals: no allocations allowed) ----------
__device__ float g_x[Tt*Dm];          // embedded + LN
__device__ float g_q[Hh*Tt*Em];       // [H, B*S, E]
__device__ float g_k[Hh*Tt*Em];
__device__ float g_v[Hh*Tt*Em];
__device__ float g_sc[Bb*Hh*Ss*Ss];   // scores / attn (in-place)
__device__ float g_ctx[Tt*Hh*Em];     // [T, H*E] concat heads
__device__ float g_t1[Tt*Dm];
__device__ float g_t2[Tt*Dm];
__device__ float g_enc[Tt*Dm];

// ---------------- reductions ----------------
__device__ __forceinline__ float warpSum(float v){
    #pragma unroll
    for (int o=16;o;o>>=1) v += __shfl_xor_sync(0xffffffffu, v, o);
    return v;
}
__device__ __forceinline__ float warpMax(float v){
    #pragma unroll
    for (int o=16;o;o>>=1) v = fmaxf(v, __shfl_xor_sync(0xffffffffu, v, o));
    return v;
}
__device__ float blockSum(float v){
    __shared__ float sh[33];
    int lane = threadIdx.x & 31, wid = threadIdx.x >> 5;
    v = warpSum(v);
    __syncthreads();
    if (lane==0) sh[wid] = v;
    __syncthreads();
    if (wid==0){
        int nw = blockDim.x >> 5;
        float t = (lane < nw) ? sh[lane] : 0.f;
        t = warpSum(t);
        if (lane==0) sh[32] = t;
    }
    __syncthreads();
    return sh[32];
}
__device__ float blockMax(float v){
    __shared__ float sh[33];
    int lane = threadIdx.x & 31, wid = threadIdx.x >> 5;
    v = warpMax(v);
    __syncthreads();
    if (lane==0) sh[wid] = v;
    __syncthreads();
    if (wid==0){
        int nw = blockDim.x >> 5;
        float t = (lane < nw) ? sh[lane] : -F_INF;
        t = warpMax(t);
        if (lane==0) sh[32] = t;
    }
    __syncthreads();
    return sh[32];
}

// ---------------- embedding + LayerNorm (one block per token) ---------------
__global__ void embed_ln_kernel(const int* __restrict__ ids,
                                const float* __restrict__ tok,
                                const float* __restrict__ seg,
                                const float* __restrict__ gamma,
                                const float* __restrict__ beta,
                                float* __restrict__ out)
{
    int t = blockIdx.x;           // 0..2047
    int s = t % Ss;
    int id = ids[t];
    int sg = (s >= Ss/2 + 1) ? 1 : 0;
    int tid = threadIdx.x;        // 256 threads, 3 elems each
    float v[3];
    float lsum = 0.f, lsq = 0.f;
    #pragma unroll
    for (int r=0; r<3; r++){
        int i = tid + r*256;
        // positional: ang = s / 10000^(2i/768); even i -> sin, odd -> cos
        double di  = (2.0 * (double)i) / 768.0;
        double ang = (double)s * exp(-di * 9.210340371976184); // ln(10000)
        float pos  = (i & 1) ? (float)cos(ang) : (float)sin(ang);
        float x = tok[(size_t)id*Dm + i] + seg[(size_t)sg*Dm + i] + pos;
        v[r] = x; lsum += x; lsq += x*x;
    }
    float sum = blockSum(lsum);
    float sq  = blockSum(lsq);
    float mean = sum * (1.f/Dm);
    float var  = sq * (1.f/Dm) - mean*mean;
    float inv  = rsqrtf(var + 1e-5f);
    #pragma unroll
    for (int r=0; r<3; r++){
        int i = tid + r*256;
        out[(size_t)t*Dm + i] = (v[r]-mean)*inv*gamma[i] + beta[i];
    }
}

// ---------------- LayerNorm (one block per row of 768) ----------------------
__global__ void ln_kernel(const float* __restrict__ in,
                          const float* __restrict__ gamma,
                          const float* __restrict__ beta,
                          float* __restrict__ out)
{
    int t = blockIdx.x;
    int tid = threadIdx.x;
    float v[3]; float lsum=0.f, lsq=0.f;
    #pragma unroll
    for (int r=0;r<3;r++){
        int i = tid + r*256;
        float x = in[(size_t)t*Dm + i];
        v[r]=x; lsum+=x; lsq+=x*x;
    }
    float sum = blockSum(lsum);
    float sq  = blockSum(lsq);
    float mean = sum * (1.f/Dm);
    float var  = sq * (1.f/Dm) - mean*mean;
    float inv  = rsqrtf(var + 1e-5f);
    #pragma unroll
    for (int r=0;r<3;r++){
        int i = tid + r*256;
        out[(size_t)t*Dm + i] = (v[r]-mean)*inv*gamma[i] + beta[i];
    }
}

// ---------------- generic tiled SGEMM: C = act(alpha*A*B(^T) + bias) --------
// 128x128 tile, BK=8, 256 threads, 8x8 per-thread. All M,N multiples of 128,
// K multiple of 8 (true for every GEMM in this net).
#define BM 128
#define BN 128
#define BK 8

template<bool TB, int ACT>
__global__ __launch_bounds__(256)
void sgemm_kernel(const float* __restrict__ Ag, const float* __restrict__ Bg,
                  const float* __restrict__ biasg, float* __restrict__ Cg,
                  int M, int N, int K, int lda, int ldb, int ldc,
                  int zdiv,
                  size_t sAo, size_t sAi, size_t sBo, size_t sBi,
                  size_t sCo, size_t sCi, size_t sbo, size_t sbi,
                  float alpha)
{
    int z  = blockIdx.z;
    int zo = z / zdiv, zi = z % zdiv;
    const float* A = Ag + (size_t)zo*sAo + (size_t)zi*sAi;
    const float* B = Bg + (size_t)zo*sBo + (size_t)zi*sBi;
    const float* bias = biasg ? (biasg + (size_t)zo*sbo + (size_t)zi*sbi) : nullptr;
    float* C = Cg + (size_t)zo*sCo + (size_t)zi*sCi;

    __shared__ float As[BK][BM];
    __shared__ float Bs[BK][BN];

    int tid = threadIdx.x;
    int tx = tid & 15, ty = tid >> 4;
    int m0 = blockIdx.y * BM, n0 = blockIdx.x * BN;

    int lrow = tid >> 1, lhalf = tid & 1;    // A (and transB) loads: 128 rows x 2 float4
    int brow = tid >> 5, bcol = (tid & 31) * 4; // plain B loads: 8 rows x 32 float4

    float acc[8][8];
    #pragma unroll
    for (int i=0;i<8;i++)
        #pragma unroll
        for (int j=0;j<8;j++) acc[i][j]=0.f;

    for (int k0 = 0; k0 < K; k0 += BK){
        float4 av = *(const float4*)&A[(size_t)(m0+lrow)*lda + k0 + lhalf*4];
        As[lhalf*4+0][lrow]=av.x; As[lhalf*4+1][lrow]=av.y;
        As[lhalf*4+2][lrow]=av.z; As[lhalf*4+3][lrow]=av.w;
        if (TB){
            float4 bv = *(const float4*)&B[(size_t)(n0+lrow)*ldb + k0 + lhalf*4];
            Bs[lhalf*4+0][lrow]=bv.x; Bs[lhalf*4+1][lrow]=bv.y;
            Bs[lhalf*4+2][lrow]=bv.z; Bs[lhalf*4+3][lrow]=bv.w;
        } else {
            float4 bv = *(const float4*)&B[(size_t)(k0+brow)*ldb + n0 + bcol];
            *(float4*)&Bs[brow][bcol] = bv;
        }
        __syncthreads();
        #pragma unroll
        for (int kk=0; kk<BK; kk++){
            float a[8], b[8];
            *(float4*)(a)   = *(const float4*)&As[kk][ty*8];
            *(float4*)(a+4) = *(const float4*)&As[kk][ty*8+4];
            *(float4*)(b)   = *(const float4*)&Bs[kk][tx*8];
            *(float4*)(b+4) = *(const float4*)&Bs[kk][tx*8+4];
            #pragma unroll
            for (int i=0;i<8;i++)
                #pragma unroll
                for (int j=0;j<8;j++)
                    acc[i][j] = fmaf(a[i], b[j], acc[i][j]);
        }
        __syncthreads();
    }

    #pragma unroll
    for (int i=0;i<8;i++){
        int m = m0 + ty*8 + i;
        float* crow = C + (size_t)m*ldc + n0 + tx*8;
        #pragma unroll
        for (int j4=0;j4<2;j4++){
            float4 o;
            float* po = &o.x;
            #pragma unroll
            for (int j=0;j<4;j++){
                int n = n0 + tx*8 + j4*4 + j;
                float vv = acc[i][j4*4+j] * alpha;
                if (bias) vv += __ldg(&bias[n]);
                if (ACT==1) vv = 0.5f*vv*(1.0f + erff(vv*0.7071067811865475f));
                po[j] = vv;
            }
            *(float4*)(crow + j4*4) = o;
        }
    }
}

// ---------------- attention softmax (one block per score row) ---------------
__global__ void attn_softmax_kernel(float* __restrict__ sc,
                                    const unsigned char* __restrict__ mask)
{
    int r = blockIdx.x;          // (b*H+h)*S + s
    int z = r / Ss;              // b*H + h
    int s = r % Ss;
    int b = z / Hh;
    float* row = sc + (size_t)r * Ss;
    const unsigned char* mrow = mask + ((size_t)b*Ss + s)*Ss;
    int tid = threadIdx.x;       // 128 threads, 4 elems each
    float v[4]; float mx = -F_INF;
    #pragma unroll
    for (int rr=0;rr<4;rr++){
        int t = tid + rr*128;
        float x = row[t];
        if (mrow[t]) x = -1e9f;
        v[rr] = x; mx = fmaxf(mx, x);
    }
    mx = blockMax(mx);
    float ls = 0.f;
    #pragma unroll
    for (int rr=0;rr<4;rr++){ v[rr] = __expf(v[rr]-mx); ls += v[rr]; }
    float sum = blockSum(ls);
    float inv = 1.f/sum;
    #pragma unroll
    for (int rr=0;rr<4;rr++){
        int t = tid + rr*128;
        row[t] = v[rr]*inv;
    }
}

// ---------------- log-softmax over vocab (one block per token) --------------
__global__ void logsoftmax_kernel(float* __restrict__ out)
{
    int t = blockIdx.x;
    float* row = out + (size_t)t * Vv;
    int tid = threadIdx.x; // 256
    float mx = -F_INF;
    for (int i=tid; i<Vv; i+=256) mx = fmaxf(mx, row[i]);
    mx = blockMax(mx);
    float ls = 0.f;
    for (int i=tid; i<Vv; i+=256) ls += __expf(row[i]-mx);
    float sum = blockSum(ls);
    float sub = mx + logf(sum);
    for (int i=tid; i<Vv; i+=256) row[i] = row[i] - sub;
}

// ---------------- cls head: enc[:,0,:] @ Wc + bc ----------------------------
__global__ void cls_kernel(const float* __restrict__ enc,
                           const float* __restrict__ Wc,
                           const float* __restrict__ bc,
                           float* __restrict__ out)
{
    int b = blockIdx.x >> 1, c = blockIdx.x & 1; // 8 blocks
    const float* row = enc + (size_t)b*Ss*Dm;    // token (b, 0)
    float lsum = 0.f;
    for (int i=threadIdx.x; i<Dm; i+=128)
        lsum += row[i] * Wc[(size_t)i*2 + c];
    float sum = blockSum(lsum);
    if (threadIdx.x==0)
        out[(size_t)Tt*Vv + b*2 + c] = sum + bc[c];
}

// ---------------- host launcher ---------------------------------------------
static inline void gemm_nt(bool tb, int act,
                           const float* A, const float* B, const float* bias, float* C,
                           int M,int N,int K,int lda,int ldb,int ldc,
                           int gz, int zdiv,
                           size_t sAo,size_t sAi,size_t sBo,size_t sBi,
                           size_t sCo,size_t sCi,size_t sbo,size_t sbi,
                           float alpha)
{
    dim3 grid(N/BN, M/BM, gz), blk(256);
    if (!tb && act==0)
        sgemm_kernel<false,0><<<grid,blk>>>(A,B,bias,C,M,N,K,lda,ldb,ldc,zdiv,
            sAo,sAi,sBo,sBi,sCo,sCi,sbo,sbi,alpha);
    else if (!tb && act==1)
        sgemm_kernel<false,1><<<grid,blk>>>(A,B,bias,C,M,N,K,lda,ldb,ldc,zdiv,
            sAo,sAi,sBo,sBi,sCo,sCi,sbo,sbi,alpha);
    else
        sgemm_kernel<true,0><<<grid,blk>>>(A,B,bias,C,M,N,K,lda,ldb,ldc,zdiv,
            sAo,sAi,sBo,sBi,sCo,sCi,sbo,sbi,alpha);
}

extern "C" void kernel_launch(void* const* d_in, const int* in_sizes, int n_in,
                              void* d_out, int out_size)
{
    (void)in_sizes; (void)n_in; (void)out_size;
    const int*   ids   = (const int*)  d_in[0];
    const unsigned char* mask = (const unsigned char*)d_in[1];
    const float* tok   = (const float*)d_in[2];
    const float* seg   = (const float*)d_in[3];
    const float* lng_e = (const float*)d_in[4];
    const float* lnb_e = (const float*)d_in[5];
    const float* Wq    = (const float*)d_in[6];
    const float* bq    = (const float*)d_in[7];
    const float* Wk    = (const float*)d_in[8];
    const float* bk    = (const float*)d_in[9];
    const float* Wv    = (const float*)d_in[10];
    const float* bv    = (const float*)d_in[11];
    const float* Wo    = (const float*)d_in[12];
    const float* bo    = (const float*)d_in[13];
    const float* lng_a = (const float*)d_in[14];
    const float* lnb_a = (const float*)d_in[15];
    const float* W1    = (const float*)d_in[16];
    const float* b1    = (const float*)d_in[17];
    const float* W2    = (const float*)d_in[18];
    const float* b2    = (const float*)d_in[19];
    const float* lng_f = (const float*)d_in[20];
    const float* lnb_f = (const float*)d_in[21];
    const float* Wp    = (const float*)d_in[22];
    const float* bp    = (const float*)d_in[23];
    const float* Wc    = (const float*)d_in[24];
    const float* bc    = (const float*)d_in[25];
    float* out = (float*)d_out;

    float *gx,*gq,*gk,*gv,*gsc,*gctx,*gt1,*gt2,*genc;
    cudaGetSymbolAddress((void**)&gx,  g_x);
    cudaGetSymbolAddress((void**)&gq,  g_q);
    cudaGetSymbolAddress((void**)&gk,  g_k);
    cudaGetSymbolAddress((void**)&gv,  g_v);
    cudaGetSymbolAddress((void**)&gsc, g_sc);
    cudaGetSymbolAddress((void**)&gctx,g_ctx);
    cudaGetSymbolAddress((void**)&gt1, g_t1);
    cudaGetSymbolAddress((void**)&gt2, g_t2);
    cudaGetSymbolAddress((void**)&genc,g_enc);

    // 1) embedding + LN
    embed_ln_kernel<<<Tt,256>>>(ids, tok, seg, lng_e, lnb_e, gx);

    // 2) QKV projections per head: z = h, C layout [H, T, E]
    size_t sW = (size_t)Dm*Em, sC = (size_t)Tt*Em;
    gemm_nt(false,0, gx,Wq,bq,gq, Tt,Em,Dm, Dm,Em,Em, Hh,1, 0,0, sW,0, sC,0, Em,0, 1.f);
    gemm_nt(false,0, gx,Wk,bk,gk, Tt,Em,Dm, Dm,Em,Em, Hh,1, 0,0, sW,0, sC,0, Em,0, 1.f);
    gemm_nt(false,0, gx,Wv,bv,gv, Tt,Em,Dm, Dm,Em,Em, Hh,1, 0,0, sW,0, sC,0, Em,0, 1.f);

    // 3) scores = Q K^T / sqrt(S): z = b*H + h
    size_t qO = (size_t)Ss*Em, qI = (size_t)Tt*Em;
    gemm_nt(true,0, gq,gk,nullptr,gsc, Ss,Ss,Em, Em,Em,Ss, Bb*Hh,Hh,
            qO,qI, qO,qI, (size_t)Hh*Ss*Ss,(size_t)Ss*Ss, 0,0,
            0.04419417382415922f);

    // 4) softmax (+mask)
    attn_softmax_kernel<<<Bb*Hh*Ss,128>>>(gsc, mask);

    // 5) ctx = attn @ V -> [T, H*E]
    gemm_nt(false,0, gsc,gv,nullptr,gctx, Ss,Em,Ss, Ss,Em,Hh*Em, Bb*Hh,Hh,
            (size_t)Hh*Ss*Ss,(size_t)Ss*Ss, qO,qI,
            (size_t)Ss*Hh*Em,(size_t)Em, 0,0, 1.f);

    // 6) attn output proj + LN
    gemm_nt(false,0, gctx,Wo,bo,gt1, Tt,Dm,Hh*Em, Hh*Em,Dm,Dm, 1,1,
            0,0, 0,0, 0,0, 0,0, 1.f);
    ln_kernel<<<Tt,256>>>(gt1, lng_a, lnb_a, gt2);

    // 7) FFN: gelu(x@W1+b1) @ W2 + b2, then LN
    gemm_nt(false,1, gt2,W1,b1,gt1, Tt,Em,Dm, Dm,Em,Em, 1,1, 0,0,0,0,0,0,0,0, 1.f);
    gemm_nt(false,0, gt1,W2,b2,gx,  Tt,Dm,Em, Em,Dm,Dm, 1,1, 0,0,0,0,0,0,0,0, 1.f);
    ln_kernel<<<Tt,256>>>(gx, lng_f, lnb_f, genc);

    // 8) vocab logits -> d_out, then log-softmax in place
    gemm_nt(false,0, genc,Wp,bp,out, Tt,Vv,Dm, Dm,Vv,Vv, 1,1, 0,0,0,0,0,0,0,0, 1.f);
    logsoftmax_kernel<<<Tt,256>>>(out);

    // 9) cls head
    cls_kernel<<<8,128>>>(genc, Wc, bc, out);
}

// round 3
// speedup vs baseline: 2.1675x; 2.1675x over previous
#include <cuda_runtime.h>
#include <math.h>
#include <stdint.h>

#define F_INF __int_as_float(0x7f800000)

// Problem dims
#define Dm 768
#define Em 768
#define Hh 12
#define Bb 4
#define Ss 512
#define Vv 32000
#define Tt (Bb*Ss)   // 2048

// ---------------- scratch (device globals: no allocations allowed) ----------
__device__ float g_x[Tt*Dm];
__device__ float g_q[Hh*Tt*Em];
__device__ float g_k[Hh*Tt*Em];
__device__ float g_v[Hh*Tt*Em];
__device__ float g_sc[Bb*Hh*Ss*Ss];
__device__ float g_ctx[Tt*Hh*Em];
__device__ float g_t1[Tt*Dm];
__device__ float g_t2[Tt*Dm];
__device__ float g_enc[Tt*Dm];

// ---------------- reductions ----------------
__device__ __forceinline__ float warpSum(float v){
    #pragma unroll
    for (int o=16;o;o>>=1) v += __shfl_xor_sync(0xffffffffu, v, o);
    return v;
}
__device__ __forceinline__ float warpMax(float v){
    #pragma unroll
    for (int o=16;o;o>>=1) v = fmaxf(v, __shfl_xor_sync(0xffffffffu, v, o));
    return v;
}
__device__ float blockSum(float v){
    __shared__ float sh[33];
    int lane = threadIdx.x & 31, wid = threadIdx.x >> 5;
    v = warpSum(v);
    __syncthreads();
    if (lane==0) sh[wid] = v;
    __syncthreads();
    if (wid==0){
        int nw = blockDim.x >> 5;
        float t = (lane < nw) ? sh[lane] : 0.f;
        t = warpSum(t);
        if (lane==0) sh[32] = t;
    }
    __syncthreads();
    return sh[32];
}
__device__ float blockMax(float v){
    __shared__ float sh[33];
    int lane = threadIdx.x & 31, wid = threadIdx.x >> 5;
    v = warpMax(v);
    __syncthreads();
    if (lane==0) sh[wid] = v;
    __syncthreads();
    if (wid==0){
        int nw = blockDim.x >> 5;
        float t = (lane < nw) ? sh[lane] : -F_INF;
        t = warpMax(t);
        if (lane==0) sh[32] = t;
    }
    __syncthreads();
    return sh[32];
}

// ---------------- embedding + LayerNorm ---------------
__global__ void embed_ln_kernel(const int* __restrict__ ids,
                                const float* __restrict__ tok,
                                const float* __restrict__ seg,
                                const float* __restrict__ gamma,
                                const float* __restrict__ beta,
                                float* __restrict__ out)
{
    int t = blockIdx.x;
    int s = t % Ss;
    int id = ids[t];
    int sg = (s >= Ss/2 + 1) ? 1 : 0;
    int tid = threadIdx.x;
    float v[3];
    float lsum = 0.f, lsq = 0.f;
    #pragma unroll
    for (int r=0; r<3; r++){
        int i = tid + r*256;
        double di  = (2.0 * (double)i) / 768.0;
        double ang = (double)s * exp(-di * 9.210340371976184);
        float pos  = (i & 1) ? (float)cos(ang) : (float)sin(ang);
        float x = tok[(size_t)id*Dm + i] + seg[(size_t)sg*Dm + i] + pos;
        v[r] = x; lsum += x; lsq += x*x;
    }
    float sum = blockSum(lsum);
    float sq  = blockSum(lsq);
    float mean = sum * (1.f/Dm);
    float var  = sq * (1.f/Dm) - mean*mean;
    float inv  = rsqrtf(var + 1e-5f);
    #pragma unroll
    for (int r=0; r<3; r++){
        int i = tid + r*256;
        out[(size_t)t*Dm + i] = (v[r]-mean)*inv*gamma[i] + beta[i];
    }
}

// ---------------- LayerNorm ----------------------
__global__ void ln_kernel(const float* __restrict__ in,
                          const float* __restrict__ gamma,
                          const float* __restrict__ beta,
                          float* __restrict__ out)
{
    int t = blockIdx.x;
    int tid = threadIdx.x;
    float v[3]; float lsum=0.f, lsq=0.f;
    #pragma unroll
    for (int r=0;r<3;r++){
        int i = tid + r*256;
        float x = in[(size_t)t*Dm + i];
        v[r]=x; lsum+=x; lsq+=x*x;
    }
    float sum = blockSum(lsum);
    float sq  = blockSum(lsq);
    float mean = sum * (1.f/Dm);
    float var  = sq * (1.f/Dm) - mean*mean;
    float inv  = rsqrtf(var + 1e-5f);
    #pragma unroll
    for (int r=0;r<3;r++){
        int i = tid + r*256;
        out[(size_t)t*Dm + i] = (v[r]-mean)*inv*gamma[i] + beta[i];
    }
}

// ================= TF32 tensor-core GEMM =================
// C = act(alpha*A*B(^T) + bias). 128x128x16 tile, 256 thr (8 warps, 2x4),
// warp tile 64x32 via m16n8k8 tf32 mma. All M,N %128==0, K %16==0.
#define BM 128
#define BN 128
#define BK 16
#define LROW 20   // 16 + 4 pad floats -> 80B row stride, LDSM conflict-free

__device__ __forceinline__ float to_tf32(float x){
    uint32_t u;
    asm("cvt.rna.tf32.f32 %0, %1;" : "=r"(u) : "f"(x));
    return __uint_as_float(u);
}
__device__ __forceinline__ void ldsm4(uint32_t& r0, uint32_t& r1, uint32_t& r2, uint32_t& r3, uint32_t addr){
    asm volatile("ldmatrix.sync.aligned.m8n8.x4.shared.b16 {%0,%1,%2,%3}, [%4];"
        : "=r"(r0),"=r"(r1),"=r"(r2),"=r"(r3) : "r"(addr));
}
__device__ __forceinline__ void mma_tf32(float& c0,float& c1,float& c2,float& c3,
                                         uint32_t a0,uint32_t a1,uint32_t a2,uint32_t a3,
                                         uint32_t b0,uint32_t b1){
    asm volatile("mma.sync.aligned.m16n8k8.row.col.f32.tf32.tf32.f32 "
        "{%0,%1,%2,%3},{%4,%5,%6,%7},{%8,%9},{%0,%1,%2,%3};"
        : "+f"(c0),"+f"(c1),"+f"(c2),"+f"(c3)
        : "r"(a0),"r"(a1),"r"(a2),"r"(a3),"r"(b0),"r"(b1));
}

template<bool TB, int ACT>
__global__ __launch_bounds__(256)
void tgemm_kernel(const float* __restrict__ Ag, const float* __restrict__ Bg,
                  const float* __restrict__ biasg, float* __restrict__ Cg,
                  int M, int N, int K, int lda, int ldb, int ldc,
                  int zdiv,
                  size_t sAo, size_t sAi, size_t sBo, size_t sBi,
                  size_t sCo, size_t sCi, size_t sbo, size_t sbi,
                  float alpha)
{
    __shared__ __align__(16) float As[BM][LROW];
    __shared__ __align__(16) float Bs[BN][LROW];

    int z  = blockIdx.z;
    int zo = z / zdiv, zi = z % zdiv;
    const float* A = Ag + (size_t)zo*sAo + (size_t)zi*sAi;
    const float* B = Bg + (size_t)zo*sBo + (size_t)zi*sBi;
    const float* bias = biasg ? (biasg + (size_t)zo*sbo + (size_t)zi*sbi) : nullptr;
    float* C = Cg + (size_t)zo*sCo + (size_t)zi*sCi;

    int m0 = blockIdx.x * BM;   // x = m tiles (fastest) -> B-tile reuse within wave
    int n0 = blockIdx.y * BN;
    int tid = threadIdx.x, lane = tid & 31, warp = tid >> 5;
    int wm = warp & 1, wn = warp >> 1;       // warp tile (wm*64, wn*32)

    float acc[4][4][4];
    #pragma unroll
    for (int i=0;i<4;i++)
        #pragma unroll
        for (int j=0;j<4;j++)
            #pragma unroll
            for (int r=0;r<4;r++) acc[i][j][r]=0.f;

    // per-thread LDSM addresses (byte offsets into shared)
    uint32_t as_base = (uint32_t)__cvta_generic_to_shared(&As[0][0]);
    uint32_t bs_base = (uint32_t)__cvta_generic_to_shared(&Bs[0][0]);
    int l15 = lane & 15, lhi = lane >> 4;
    uint32_t a_off[4];
    #pragma unroll
    for (int i=0;i<4;i++)
        a_off[i] = as_base + (uint32_t)(((wm*64 + i*16 + l15)*LROW + 4*lhi)*4);
    int brow = (lane & 7) + ((lane & 16) ? 8 : 0);
    int bcol = (lane & 8) ? 4 : 0;
    uint32_t b_off[2];
    #pragma unroll
    for (int jj=0;jj<2;jj++)
        b_off[jj] = bs_base + (uint32_t)(((wn*32 + jj*16 + brow)*LROW + bcol)*4);

    // global load indices
    int arow0 = tid >> 2, acol = (tid & 3) * 4;        // A / TB-B: 2 rows per thread
    int nkk   = (tid & 7) * 2;                          // non-TB B: k pair
    int nn4   = (tid >> 3) * 4;                         // non-TB B: n group of 4

    for (int k0 = 0; k0 < K; k0 += BK){
        #pragma unroll
        for (int r=0;r<2;r++){
            int row = arow0 + r*64;
            const float4 v = *(const float4*)&A[(size_t)(m0+row)*lda + k0 + acol];
            float4 w; w.x=to_tf32(v.x); w.y=to_tf32(v.y); w.z=to_tf32(v.z); w.w=to_tf32(v.w);
            *(float4*)&As[row][acol] = w;
        }
        if (TB){
            #pragma unroll
            for (int r=0;r<2;r++){
                int row = arow0 + r*64;
                const float4 v = *(const float4*)&B[(size_t)(n0+row)*ldb + k0 + acol];
                float4 w; w.x=to_tf32(v.x); w.y=to_tf32(v.y); w.z=to_tf32(v.z); w.w=to_tf32(v.w);
                *(float4*)&Bs[row][acol] = w;
            }
        } else {
            #pragma unroll
            for (int r=0;r<2;r++){
                int kk = nkk + r;
                const float4 v = *(const float4*)&B[(size_t)(k0+kk)*ldb + n0 + nn4];
                Bs[nn4+0][kk] = to_tf32(v.x);
                Bs[nn4+1][kk] = to_tf32(v.y);
                Bs[nn4+2][kk] = to_tf32(v.z);
                Bs[nn4+3][kk] = to_tf32(v.w);
            }
        }
        __syncthreads();

        #pragma unroll
        for (int kk=0; kk<BK; kk+=8){
            uint32_t a[4][4], bf[4][2];
            #pragma unroll
            for (int i=0;i<4;i++)
                ldsm4(a[i][0],a[i][1],a[i][2],a[i][3], a_off[i] + kk*4);
            #pragma unroll
            for (int jj=0;jj<2;jj++)
                ldsm4(bf[2*jj][0],bf[2*jj][1],bf[2*jj+1][0],bf[2*jj+1][1], b_off[jj] + kk*4);
            #pragma unroll
            for (int i=0;i<4;i++)
                #pragma unroll
                for (int j=0;j<4;j++)
                    mma_tf32(acc[i][j][0],acc[i][j][1],acc[i][j][2],acc[i][j][3],
                             a[i][0],a[i][1],a[i][2],a[i][3], bf[j][0],bf[j][1]);
        }
        __syncthreads();
    }

    // epilogue
    int g = lane >> 2, tg = lane & 3;
    #pragma unroll
    for (int i=0;i<4;i++){
        #pragma unroll
        for (int j=0;j<4;j++){
            int ncol = n0 + wn*32 + j*8 + 2*tg;
            float b0v = bias ? __ldg(&bias[ncol])   : 0.f;
            float b1v = bias ? __ldg(&bias[ncol+1]) : 0.f;
            #pragma unroll
            for (int h=0;h<2;h++){
                int mrow = m0 + wm*64 + i*16 + g + h*8;
                float v0 = acc[i][j][2*h+0]*alpha + b0v;
                float v1 = acc[i][j][2*h+1]*alpha + b1v;
                if (ACT==1){
                    v0 = 0.5f*v0*(1.0f + erff(v0*0.7071067811865475f));
                    v1 = 0.5f*v1*(1.0f + erff(v1*0.7071067811865475f));
                }
                float2 o; o.x=v0; o.y=v1;
                *(float2*)&C[(size_t)mrow*ldc + ncol] = o;
            }
        }
    }
}

// ---------------- attention softmax ---------------
__global__ void attn_softmax_kernel(float* __restrict__ sc,
                                    const unsigned char* __restrict__ mask)
{
    int r = blockIdx.x;
    int z = r / Ss;
    int s = r % Ss;
    int b = z / Hh;
    float* row = sc + (size_t)r * Ss;
    const unsigned char* mrow = mask + ((size_t)b*Ss + s)*Ss;
    int tid = threadIdx.x;
    float v[4]; float mx = -F_INF;
    #pragma unroll
    for (int rr=0;rr<4;rr++){
        int t = tid + rr*128;
        float x = row[t];
        if (mrow[t]) x = -1e9f;
        v[rr] = x; mx = fmaxf(mx, x);
    }
    mx = blockMax(mx);
    float ls = 0.f;
    #pragma unroll
    for (int rr=0;rr<4;rr++){ v[rr] = __expf(v[rr]-mx); ls += v[rr]; }
    float sum = blockSum(ls);
    float inv = 1.f/sum;
    #pragma unroll
    for (int rr=0;rr<4;rr++){
        int t = tid + rr*128;
        row[t] = v[rr]*inv;
    }
}

// ---------------- log-softmax over vocab --------------
__global__ void logsoftmax_kernel(float* __restrict__ out)
{
    int t = blockIdx.x;
    float* row = out + (size_t)t * Vv;
    int tid = threadIdx.x;
    float mx = -F_INF;
    for (int i=tid; i<Vv; i+=256) mx = fmaxf(mx, row[i]);
    mx = blockMax(mx);
    float ls = 0.f;
    for (int i=tid; i<Vv; i+=256) ls += __expf(row[i]-mx);
    float sum = blockSum(ls);
    float sub = mx + logf(sum);
    for (int i=tid; i<Vv; i+=256) row[i] = row[i] - sub;
}

// ---------------- cls head ----------------------------
__global__ void cls_kernel(const float* __restrict__ enc,
                           const float* __restrict__ Wc,
                           const float* __restrict__ bc,
                           float* __restrict__ out)
{
    int b = blockIdx.x >> 1, c = blockIdx.x & 1;
    const float* row = enc + (size_t)b*Ss*Dm;
    float lsum = 0.f;
    for (int i=threadIdx.x; i<Dm; i+=128)
        lsum += row[i] * Wc[(size_t)i*2 + c];
    float sum = blockSum(lsum);
    if (threadIdx.x==0)
        out[(size_t)Tt*Vv + b*2 + c] = sum + bc[c];
}

// ---------------- host launcher ---------------------------------------------
static inline void gemm_nt(bool tb, int act,
                           const float* A, const float* B, const float* bias, float* C,
                           int M,int N,int K,int lda,int ldb,int ldc,
                           int gz, int zdiv,
                           size_t sAo,size_t sAi,size_t sBo,size_t sBi,
                           size_t sCo,size_t sCi,size_t sbo,size_t sbi,
                           float alpha)
{
    dim3 grid(M/BM, N/BN, gz), blk(256);
    if (!tb && act==0)
        tgemm_kernel<false,0><<<grid,blk>>>(A,B,bias,C,M,N,K,lda,ldb,ldc,zdiv,
            sAo,sAi,sBo,sBi,sCo,sCi,sbo,sbi,alpha);
    else if (!tb && act==1)
        tgemm_kernel<false,1><<<grid,blk>>>(A,B,bias,C,M,N,K,lda,ldb,ldc,zdiv,
            sAo,sAi,sBo,sBi,sCo,sCi,sbo,sbi,alpha);
    else
        tgemm_kernel<true,0><<<grid,blk>>>(A,B,bias,C,M,N,K,lda,ldb,ldc,zdiv,
            sAo,sAi,sBo,sBi,sCo,sCi,sbo,sbi,alpha);
}

extern "C" void kernel_launch(void* const* d_in, const int* in_sizes, int n_in,
                              void* d_out, int out_size)
{
    (void)in_sizes; (void)n_in; (void)out_size;
    const int*   ids   = (const int*)  d_in[0];
    const unsigned char* mask = (const unsigned char*)d_in[1];
    const float* tok   = (const float*)d_in[2];
    const float* seg   = (const float*)d_in[3];
    const float* lng_e = (const float*)d_in[4];
    const float* lnb_e = (const float*)d_in[5];
    const float* Wq    = (const float*)d_in[6];
    const float* bq    = (const float*)d_in[7];
    const float* Wk    = (const float*)d_in[8];
    const float* bk    = (const float*)d_in[9];
    const float* Wv    = (const float*)d_in[10];
    const float* bv    = (const float*)d_in[11];
    const float* Wo    = (const float*)d_in[12];
    const float* bo    = (const float*)d_in[13];
    const float* lng_a = (const float*)d_in[14];
    const float* lnb_a = (const float*)d_in[15];
    const float* W1    = (const float*)d_in[16];
    const float* b1    = (const float*)d_in[17];
    const float* W2    = (const float*)d_in[18];
    const float* b2    = (const float*)d_in[19];
    const float* lng_f = (const float*)d_in[20];
    const float* lnb_f = (const float*)d_in[21];
    const float* Wp    = (const float*)d_in[22];
    const float* bp    = (const float*)d_in[23];
    const float* Wc    = (const float*)d_in[24];
    const float* bc    = (const float*)d_in[25];
    float* out = (float*)d_out;

    float *gx,*gq,*gk,*gv,*gsc,*gctx,*gt1,*gt2,*genc;
    cudaGetSymbolAddress((void**)&gx,  g_x);
    cudaGetSymbolAddress((void**)&gq,  g_q);
    cudaGetSymbolAddress((void**)&gk,  g_k);
    cudaGetSymbolAddress((void**)&gv,  g_v);
    cudaGetSymbolAddress((void**)&gsc, g_sc);
    cudaGetSymbolAddress((void**)&gctx,g_ctx);
    cudaGetSymbolAddress((void**)&gt1, g_t1);
    cudaGetSymbolAddress((void**)&gt2, g_t2);
    cudaGetSymbolAddress((void**)&genc,g_enc);

    // 1) embedding + LN
    embed_ln_kernel<<<Tt,256>>>(ids, tok, seg, lng_e, lnb_e, gx);

    // 2) QKV projections per head: z = h, C layout [H, T, E]
    size_t sW = (size_t)Dm*Em, sC = (size_t)Tt*Em;
    gemm_nt(false,0, gx,Wq,bq,gq, Tt,Em,Dm, Dm,Em,Em, Hh,1, 0,0, sW,0, sC,0, Em,0, 1.f);
    gemm_nt(false,0, gx,Wk,bk,gk, Tt,Em,Dm, Dm,Em,Em, Hh,1, 0,0, sW,0, sC,0, Em,0, 1.f);
    gemm_nt(false,0, gx,Wv,bv,gv, Tt,Em,Dm, Dm,Em,Em, Hh,1, 0,0, sW,0, sC,0, Em,0, 1.f);

    // 3) scores = Q K^T / sqrt(S): z = b*H + h
    size_t qO = (size_t)Ss*Em, qI = (size_t)Tt*Em;
    gemm_nt(true,0, gq,gk,nullptr,gsc, Ss,Ss,Em, Em,Em,Ss, Bb*Hh,Hh,
            qO,qI, qO,qI, (size_t)Hh*Ss*Ss,(size_t)Ss*Ss, 0,0,
            0.04419417382415922f);

    // 4) softmax (+mask)
    attn_softmax_kernel<<<Bb*Hh*Ss,128>>>(gsc, mask);

    // 5) ctx = attn @ V -> [T, H*E]
    gemm_nt(false,0, gsc,gv,nullptr,gctx, Ss,Em,Ss, Ss,Em,Hh*Em, Bb*Hh,Hh,
            (size_t)Hh*Ss*Ss,(size_t)Ss*Ss, qO,qI,
            (size_t)Ss*Hh*Em,(size_t)Em, 0,0, 1.f);

    // 6) attn output proj + LN
    gemm_nt(false,0, gctx,Wo,bo,gt1, Tt,Dm,Hh*Em, Hh*Em,Dm,Dm, 1,1,
            0,0, 0,0, 0,0, 0,0, 1.f);
    ln_kernel<<<Tt,256>>>(gt1, lng_a, lnb_a, gt2);

    // 7) FFN: gelu(x@W1+b1) @ W2 + b2, then LN
    gemm_nt(false,1, gt2,W1,b1,gt1, Tt,Em,Dm, Dm,Em,Em, 1,1, 0,0,0,0,0,0,0,0, 1.f);
    gemm_nt(false,0, gt1,W2,b2,gx,  Tt,Dm,Em, Em,Dm,Dm, 1,1, 0,0,0,0,0,0,0,0, 1.f);
    ln_kernel<<<Tt,256>>>(gx, lng_f, lnb_f, genc);

    // 8) vocab logits -> d_out, then log-softmax in place
    gemm_nt(false,0, genc,Wp,bp,out, Tt,Vv,Dm, Dm,Vv,Vv, 1,1, 0,0,0,0,0,0,0,0, 1.f);
    logsoftmax_kernel<<<Tt,256>>>(out);

    // 9) cls head
    cls_kernel<<<8,128>>>(genc, Wc, bc, out);
}

// round 5
// speedup vs baseline: 3.6946x; 1.7045x over previous
#include <cuda_runtime.h>
#include <math.h>
#include <stdint.h>

#define F_INF __int_as_float(0x7f800000)

// Problem dims
#define Dm 768
#define Em 768
#define Hh 12
#define Bb 4
#define Ss 512
#define Vv 32000
#define Tt (Bb*Ss)   // 2048

// ---------------- scratch (device globals) ----------------------------------
__device__ float g_x[Tt*Dm];
__device__ float g_q[Hh*Tt*Em];
__device__ float g_k[Hh*Tt*Em];
__device__ float g_v[Hh*Tt*Em];
__device__ float g_vT[Hh*Em*Tt];      // V transposed per head: [H][E][T]
__device__ float g_sc[Bb*Hh*Ss*Ss];
__device__ float g_ctx[Tt*Hh*Em];
__device__ float g_t1[Tt*Dm];
__device__ float g_t2[Tt*Dm];
__device__ float g_enc[Tt*Dm];
// transposed (tf32-rounded) weights, [N][K] layout
__device__ float g_wqt[Hh*Em*Dm];
__device__ float g_wkt[Hh*Em*Dm];
__device__ float g_wvt[Hh*Em*Dm];
__device__ float g_wot[Dm*Hh*Em];     // [768][9216]
__device__ float g_w1t[Em*Dm];
__device__ float g_w2t[Dm*Em];
__device__ float g_wpt[Vv*Dm];        // [32000][768]

// ---------------- helpers ----------------
__device__ __forceinline__ float to_tf32(float x){
    uint32_t u;
    asm("cvt.rna.tf32.f32 %0, %1;" : "=r"(u) : "f"(x));
    return __uint_as_float(u);
}
__device__ __forceinline__ float warpSum(float v){
    #pragma unroll
    for (int o=16;o;o>>=1) v += __shfl_xor_sync(0xffffffffu, v, o);
    return v;
}
__device__ __forceinline__ float warpMax(float v){
    #pragma unroll
    for (int o=16;o;o>>=1) v = fmaxf(v, __shfl_xor_sync(0xffffffffu, v, o));
    return v;
}
__device__ float blockSum(float v){
    __shared__ float sh[33];
    int lane = threadIdx.x & 31, wid = threadIdx.x >> 5;
    v = warpSum(v);
    __syncthreads();
    if (lane==0) sh[wid] = v;
    __syncthreads();
    if (wid==0){
        int nw = blockDim.x >> 5;
        float t = (lane < nw) ? sh[lane] : 0.f;
        t = warpSum(t);
        if (lane==0) sh[32] = t;
    }
    __syncthreads();
    return sh[32];
}
__device__ float blockMax(float v){
    __shared__ float sh[33];
    int lane = threadIdx.x & 31, wid = threadIdx.x >> 5;
    v = warpMax(v);
    __syncthreads();
    if (lane==0) sh[wid] = v;
    __syncthreads();
    if (wid==0){
        int nw = blockDim.x >> 5;
        float t = (lane < nw) ? sh[lane] : -F_INF;
        t = warpMax(t);
        if (lane==0) sh[32] = t;
    }
    __syncthreads();
    return sh[32];
}

// ---------------- transpose + tf32 round: src[R][C] -> dst[C][R] ------------
__global__ void transpose_round_kernel(const float* __restrict__ src,
                                       float* __restrict__ dst,
                                       int R, int C)
{
    __shared__ float tile[32][33];
    int z = blockIdx.z;
    src += (size_t)z*R*C;
    dst += (size_t)z*R*C;
    int c0 = blockIdx.x*32, r0 = blockIdx.y*32;
    int tx = threadIdx.x, ty = threadIdx.y;     // 32 x 8
    #pragma unroll
    for (int i=0;i<32;i+=8)
        tile[ty+i][tx] = to_tf32(src[(size_t)(r0+ty+i)*C + c0+tx]);
    __syncthreads();
    #pragma unroll
    for (int i=0;i<32;i+=8)
        dst[(size_t)(c0+ty+i)*R + r0+tx] = tile[tx][ty+i];
}

// ---------------- embedding + LayerNorm (round output) ----------------------
__global__ void embed_ln_kernel(const int* __restrict__ ids,
                                const float* __restrict__ tok,
                                const float* __restrict__ seg,
                                const float* __restrict__ gamma,
                                const float* __restrict__ beta,
                                float* __restrict__ out)
{
    int t = blockIdx.x;
    int s = t % Ss;
    int id = ids[t];
    int sg = (s >= Ss/2 + 1) ? 1 : 0;
    int tid = threadIdx.x;
    float v[3];
    float lsum = 0.f, lsq = 0.f;
    #pragma unroll
    for (int r=0; r<3; r++){
        int i = tid + r*256;
        double di  = (2.0 * (double)i) / 768.0;
        double ang = (double)s * exp(-di * 9.210340371976184);
        float pos  = (i & 1) ? (float)cos(ang) : (float)sin(ang);
        float x = tok[(size_t)id*Dm + i] + seg[(size_t)sg*Dm + i] + pos;
        v[r] = x; lsum += x; lsq += x*x;
    }
    float sum = blockSum(lsum);
    float sq  = blockSum(lsq);
    float mean = sum * (1.f/Dm);
    float var  = sq * (1.f/Dm) - mean*mean;
    float inv  = rsqrtf(var + 1e-5f);
    #pragma unroll
    for (int r=0; r<3; r++){
        int i = tid + r*256;
        out[(size_t)t*Dm + i] = to_tf32((v[r]-mean)*inv*gamma[i] + beta[i]);
    }
}

// ---------------- LayerNorm (round output) ----------------------------------
__global__ void ln_kernel(const float* __restrict__ in,
                          const float* __restrict__ gamma,
                          const float* __restrict__ beta,
                          float* __restrict__ out)
{
    int t = blockIdx.x;
    int tid = threadIdx.x;
    float v[3]; float lsum=0.f, lsq=0.f;
    #pragma unroll
    for (int r=0;r<3;r++){
        int i = tid + r*256;
        float x = in[(size_t)t*Dm + i];
        v[r]=x; lsum+=x; lsq+=x*x;
    }
    float sum = blockSum(lsum);
    float sq  = blockSum(lsq);
    float mean = sum * (1.f/Dm);
    float var  = sq * (1.f/Dm) - mean*mean;
    float inv  = rsqrtf(var + 1e-5f);
    #pragma unroll
    for (int r=0;r<3;r++){
        int i = tid + r*256;
        out[(size_t)t*Dm + i] = to_tf32((v[r]-mean)*inv*gamma[i] + beta[i]);
    }
}

// ================= TF32 tensor-core GEMM, TB-only, cp.async 3-stage ==========
// C = act(alpha * A * B^T + bias). A [M][K] rows m, B [N][K] rows n.
// 128x128x16 block tile, 128 threads (4 warps 2x2), warp tile 64x64.
#define BM 128
#define BN 128
#define BK 16
#define LROW 20                       // floats per smem row (80B), LDSM conflict-free
#define STAGE_FLOATS (2*BM*LROW)      // A + B per stage = 5120 floats
#define STAGE_BYTES  (STAGE_FLOATS*4) // 20480
#define SMEM_BYTES   (3*STAGE_BYTES)  // 61440

__device__ __forceinline__ void ldsm4(uint32_t& r0, uint32_t& r1, uint32_t& r2, uint32_t& r3, uint32_t addr){
    asm volatile("ldmatrix.sync.aligned.m8n8.x4.shared.b16 {%0,%1,%2,%3}, [%4];"
        : "=r"(r0),"=r"(r1),"=r"(r2),"=r"(r3) : "r"(addr));
}
__device__ __forceinline__ void mma_tf32(float& c0,float& c1,float& c2,float& c3,
                                         uint32_t a0,uint32_t a1,uint32_t a2,uint32_t a3,
                                         uint32_t b0,uint32_t b1){
    asm volatile("mma.sync.aligned.m16n8k8.row.col.f32.tf32.tf32.f32 "
        "{%0,%1,%2,%3},{%4,%5,%6,%7},{%8,%9},{%0,%1,%2,%3};"
        : "+f"(c0),"+f"(c1),"+f"(c2),"+f"(c3)
        : "r"(a0),"r"(a1),"r"(a2),"r"(a3),"r"(b0),"r"(b1));
}
__device__ __forceinline__ void cp16(uint32_t dst, const float* src){
    asm volatile("cp.async.cg.shared.global [%0], [%1], 16;" :: "r"(dst), "l"(src));
}

template<int ACT, int ROUND>
__global__ __launch_bounds__(128)
void tgemm_kernel(const float* __restrict__ Ag, const float* __restrict__ Bg,
                  const float* __restrict__ biasg, float* __restrict__ Cg,
                  int K, int lda, int ldb, int ldc,
                  int zdiv,
                  size_t sAo, size_t sAi, size_t sBo, size_t sBi,
                  size_t sCo, size_t sCi, size_t sbo, size_t sbi,
                  float alpha)
{
    extern __shared__ float dsm[];
    uint32_t s_base = (uint32_t)__cvta_generic_to_shared(dsm);

    int z  = blockIdx.z;
    int zo = z / zdiv, zi = z % zdiv;
    const float* A = Ag + (size_t)zo*sAo + (size_t)zi*sAi;
    const float* B = Bg + (size_t)zo*sBo + (size_t)zi*sBi;
    const float* bias = biasg ? (biasg + (size_t)zo*sbo + (size_t)zi*sbi) : nullptr;
    float* C = Cg + (size_t)zo*sCo + (size_t)zi*sCi;

    int m0 = blockIdx.x * BM;
    int n0 = blockIdx.y * BN;
    int tid = threadIdx.x, lane = tid & 31, warp = tid >> 5;
    int wm = warp & 1, wn = warp >> 1;      // warp tile (wm*64, wn*64)

    float acc[4][8][4];
    #pragma unroll
    for (int i=0;i<4;i++)
        #pragma unroll
        for (int j=0;j<8;j++)
            #pragma unroll
            for (int r=0;r<4;r++) acc[i][j][r]=0.f;

    // ldsm byte offsets relative to stage base
    int l15 = lane & 15, lhi = lane >> 4;
    uint32_t a_rel[4];
    #pragma unroll
    for (int i=0;i<4;i++)
        a_rel[i] = (uint32_t)(((wm*64 + i*16 + l15)*LROW + 4*lhi)*4);
    int brow = (lane & 7) + ((lane & 16) ? 8 : 0);
    int bcol = (lane & 8) ? 4 : 0;
    uint32_t b_rel[4];
    #pragma unroll
    for (int jj=0;jj<4;jj++)
        b_rel[jj] = (uint32_t)(((wn*64 + jj*16 + brow)*LROW + bcol)*4 + BM*LROW*4);

    // cp.async loader: per thread 4 A chunks + 4 B chunks per stage
    int nk = K / BK;
    auto load_stage = [&](int st, int k0){
        uint32_t sb = s_base + (uint32_t)st*STAGE_BYTES;
        #pragma unroll
        for (int i=0;i<4;i++){
            int c = tid + 128*i;
            int r = c >> 2, cc = c & 3;
            cp16(sb + (uint32_t)((r*LROW + cc*4)*4),
                 A + (size_t)(m0+r)*lda + k0 + cc*4);
        }
        #pragma unroll
        for (int i=0;i<4;i++){
            int c = tid + 128*i;
            int r = c >> 2, cc = c & 3;
            cp16(sb + (uint32_t)(BM*LROW*4 + (r*LROW + cc*4)*4),
                 B + (size_t)(n0+r)*ldb + k0 + cc*4);
        }
    };

    load_stage(0, 0);
    asm volatile("cp.async.commit_group;");
    load_stage(1, BK);
    asm volatile("cp.async.commit_group;");

    int st = 0;
    for (int i=0; i<nk; i++){
        asm volatile("cp.async.wait_group 1;");
        __syncthreads();
        if (i+2 < nk) load_stage((st+2)%3, (i+2)*BK);
        asm volatile("cp.async.commit_group;");

        uint32_t abase = s_base + (uint32_t)st*STAGE_BYTES;
        #pragma unroll
        for (int kk=0; kk<BK; kk+=8){
            uint32_t a[4][4], bf[8][2];
            #pragma unroll
            for (int ii=0;ii<4;ii++)
                ldsm4(a[ii][0],a[ii][1],a[ii][2],a[ii][3], abase + a_rel[ii] + kk*4);
            #pragma unroll
            for (int jj=0;jj<4;jj++)
                ldsm4(bf[2*jj][0],bf[2*jj][1],bf[2*jj+1][0],bf[2*jj+1][1], abase + b_rel[jj] + kk*4);
            #pragma unroll
            for (int ii=0;ii<4;ii++)
                #pragma unroll
                for (int jj=0;jj<8;jj++)
                    mma_tf32(acc[ii][jj][0],acc[ii][jj][1],acc[ii][jj][2],acc[ii][jj][3],
                             a[ii][0],a[ii][1],a[ii][2],a[ii][3], bf[jj][0],bf[jj][1]);
        }
        st = (st+1)%3;
    }

    // epilogue
    int g = lane >> 2, tg = lane & 3;
    #pragma unroll
    for (int i=0;i<4;i++){
        #pragma unroll
        for (int j=0;j<8;j++){
            int ncol = n0 + wn*64 + j*8 + 2*tg;
            float b0v = bias ? __ldg(&bias[ncol])   : 0.f;
            float b1v = bias ? __ldg(&bias[ncol+1]) : 0.f;
            #pragma unroll
            for (int h=0;h<2;h++){
                int mrow = m0 + wm*64 + i*16 + g + h*8;
                float v0 = acc[i][j][2*h+0]*alpha + b0v;
                float v1 = acc[i][j][2*h+1]*alpha + b1v;
                if (ACT==1){
                    v0 = 0.5f*v0*(1.0f + erff(v0*0.7071067811865475f));
                    v1 = 0.5f*v1*(1.0f + erff(v1*0.7071067811865475f));
                }
                if (ROUND){ v0 = to_tf32(v0); v1 = to_tf32(v1); }
                float2 o; o.x=v0; o.y=v1;
                *(float2*)&C[(size_t)mrow*ldc + ncol] = o;
            }
        }
    }
}

// ---------------- attention softmax (round output) ---------------
__global__ void attn_softmax_kernel(float* __restrict__ sc,
                                    const unsigned char* __restrict__ mask)
{
    int r = blockIdx.x;
    int z = r / Ss;
    int s = r % Ss;
    int b = z / Hh;
    float* row = sc + (size_t)r * Ss;
    const unsigned char* mrow = mask + ((size_t)b*Ss + s)*Ss;
    int tid = threadIdx.x;
    float v[4]; float mx = -F_INF;
    #pragma unroll
    for (int rr=0;rr<4;rr++){
        int t = tid + rr*128;
        float x = row[t];
        if (mrow[t]) x = -1e9f;
        v[rr] = x; mx = fmaxf(mx, x);
    }
    mx = blockMax(mx);
    float ls = 0.f;
    #pragma unroll
    for (int rr=0;rr<4;rr++){ v[rr] = __expf(v[rr]-mx); ls += v[rr]; }
    float sum = blockSum(ls);
    float inv = 1.f/sum;
    #pragma unroll
    for (int rr=0;rr<4;rr++){
        int t = tid + rr*128;
        row[t] = to_tf32(v[rr]*inv);
    }
}

// ---------------- log-softmax over vocab (register-cached) -------------------
__global__ __launch_bounds__(512) void logsoftmax_kernel(float* __restrict__ out)
{
    const int NV4 = Vv/4;   // 8000
    int t = blockIdx.x;
    float4* row = (float4*)(out + (size_t)t * Vv);
    int tid = threadIdx.x;
    float4 v[16];
    float mx = -F_INF;
    #pragma unroll
    for (int k=0;k<16;k++){
        int i = tid + k*512;
        if (i < NV4){
            v[k] = row[i];
            mx = fmaxf(mx, fmaxf(fmaxf(v[k].x,v[k].y), fmaxf(v[k].z,v[k].w)));
        }
    }
    mx = blockMax(mx);
    float ls = 0.f;
    #pragma unroll
    for (int k=0;k<16;k++){
        int i = tid + k*512;
        if (i < NV4)
            ls += __expf(v[k].x-mx)+__expf(v[k].y-mx)+__expf(v[k].z-mx)+__expf(v[k].w-mx);
    }
    float sum = blockSum(ls);
    float sub = mx + logf(sum);
    #pragma unroll
    for (int k=0;k<16;k++){
        int i = tid + k*512;
        if (i < NV4){
            float4 o; o.x=v[k].x-sub; o.y=v[k].y-sub; o.z=v[k].z-sub; o.w=v[k].w-sub;
            row[i] = o;
        }
    }
}

// ---------------- cls head ----------------------------
__global__ void cls_kernel(const float* __restrict__ enc,
                           const float* __restrict__ Wc,
                           const float* __restrict__ bc,
                           float* __restrict__ out)
{
    int b = blockIdx.x >> 1, c = blockIdx.x & 1;
    const float* row = enc + (size_t)b*Ss*Dm;
    float lsum = 0.f;
    for (int i=threadIdx.x; i<Dm; i+=128)
        lsum += row[i] * Wc[(size_t)i*2 + c];
    float sum = blockSum(lsum);
    if (threadIdx.x==0)
        out[(size_t)Tt*Vv + b*2 + c] = sum + bc[c];
}

// ---------------- host launcher ---------------------------------------------
static inline void gemm_tb(int act, int round,
                           const float* A, const float* B, const float* bias, float* C,
                           int M,int N,int K,int lda,int ldb,int ldc,
                           int gz, int zdiv,
                           size_t sAo,size_t sAi,size_t sBo,size_t sBi,
                           size_t sCo,size_t sCi,size_t sbo,size_t sbi,
                           float alpha)
{
    dim3 grid(M/BM, N/BN, gz), blk(128);
    if (act==0 && round==1){
        cudaFuncSetAttribute(tgemm_kernel<0,1>, cudaFuncAttributeMaxDynamicSharedMemorySize, SMEM_BYTES);
        tgemm_kernel<0,1><<<grid,blk,SMEM_BYTES>>>(A,B,bias,C,K,lda,ldb,ldc,zdiv,
            sAo,sAi,sBo,sBi,sCo,sCi,sbo,sbi,alpha);
    } else if (act==0){
        cudaFuncSetAttribute(tgemm_kernel<0,0>, cudaFuncAttributeMaxDynamicSharedMemorySize, SMEM_BYTES);
        tgemm_kernel<0,0><<<grid,blk,SMEM_BYTES>>>(A,B,bias,C,K,lda,ldb,ldc,zdiv,
            sAo,sAi,sBo,sBi,sCo,sCi,sbo,sbi,alpha);
    } else {
        cudaFuncSetAttribute(tgemm_kernel<1,1>, cudaFuncAttributeMaxDynamicSharedMemorySize, SMEM_BYTES);
        tgemm_kernel<1,1><<<grid,blk,SMEM_BYTES>>>(A,B,bias,C,K,lda,ldb,ldc,zdiv,
            sAo,sAi,sBo,sBi,sCo,sCi,sbo,sbi,alpha);
    }
}

extern "C" void kernel_launch(void* const* d_in, const int* in_sizes, int n_in,
                              void* d_out, int out_size)
{
    (void)in_sizes; (void)n_in; (void)out_size;
    const int*   ids   = (const int*)  d_in[0];
    const unsigned char* mask = (const unsigned char*)d_in[1];
    const float* tok   = (const float*)d_in[2];
    const float* seg   = (const float*)d_in[3];
    const float* lng_e = (const float*)d_in[4];
    const float* lnb_e = (const float*)d_in[5];
    const float* Wq    = (const float*)d_in[6];
    const float* bq    = (const float*)d_in[7];
    const float* Wk    = (const float*)d_in[8];
    const float* bk    = (const float*)d_in[9];
    const float* Wv    = (const float*)d_in[10];
    const float* bv    = (const float*)d_in[11];
    const float* Wo    = (const float*)d_in[12];
    const float* bo    = (const float*)d_in[13];
    const float* lng_a = (const float*)d_in[14];
    const float* lnb_a = (const float*)d_in[15];
    const float* W1    = (const float*)d_in[16];
    const float* b1    = (const float*)d_in[17];
    const float* W2    = (const float*)d_in[18];
    const float* b2    = (const float*)d_in[19];
    const float* lng_f = (const float*)d_in[20];
    const float* lnb_f = (const float*)d_in[21];
    const float* Wp    = (const float*)d_in[22];
    const float* bp    = (const float*)d_in[23];
    const float* Wc    = (const float*)d_in[24];
    const float* bc    = (const float*)d_in[25];
    float* out = (float*)d_out;

    float *gx,*gq,*gk,*gv,*gvT,*gsc,*gctx,*gt1,*gt2,*genc;
    float *wqt,*wkt,*wvt,*wot,*w1t,*w2t,*wpt;
    cudaGetSymbolAddress((void**)&gx,  g_x);
    cudaGetSymbolAddress((void**)&gq,  g_q);
    cudaGetSymbolAddress((void**)&gk,  g_k);
    cudaGetSymbolAddress((void**)&gv,  g_v);
    cudaGetSymbolAddress((void**)&gvT, g_vT);
    cudaGetSymbolAddress((void**)&gsc, g_sc);
    cudaGetSymbolAddress((void**)&gctx,g_ctx);
    cudaGetSymbolAddress((void**)&gt1, g_t1);
    cudaGetSymbolAddress((void**)&gt2, g_t2);
    cudaGetSymbolAddress((void**)&genc,g_enc);
    cudaGetSymbolAddress((void**)&wqt, g_wqt);
    cudaGetSymbolAddress((void**)&wkt, g_wkt);
    cudaGetSymbolAddress((void**)&wvt, g_wvt);
    cudaGetSymbolAddress((void**)&wot, g_wot);
    cudaGetSymbolAddress((void**)&w1t, g_w1t);
    cudaGetSymbolAddress((void**)&w2t, g_w2t);
    cudaGetSymbolAddress((void**)&wpt, g_wpt);

    dim3 tb(32,8);
    // weight transposes + tf32 rounding (all independent)
    transpose_round_kernel<<<dim3(Em/32, Dm/32, Hh), tb>>>(Wq, wqt, Dm, Em);
    transpose_round_kernel<<<dim3(Em/32, Dm/32, Hh), tb>>>(Wk, wkt, Dm, Em);
    transpose_round_kernel<<<dim3(Em/32, Dm/32, Hh), tb>>>(Wv, wvt, Dm, Em);
    transpose_round_kernel<<<dim3(Dm/32, (Hh*Em)/32, 1), tb>>>(Wo, wot, Hh*Em, Dm);
    transpose_round_kernel<<<dim3(Em/32, Dm/32, 1), tb>>>(W1, w1t, Dm, Em);
    transpose_round_kernel<<<dim3(Dm/32, Em/32, 1), tb>>>(W2, w2t, Em, Dm);
    transpose_round_kernel<<<dim3(Vv/32, Dm/32, 1), tb>>>(Wp, wpt, Dm, Vv);

    // 1) embedding + LN (tf32-rounded)
    embed_ln_kernel<<<Tt,256>>>(ids, tok, seg, lng_e, lnb_e, gx);

    // 2) QKV projections per head (B = transposed weights, TB)
    size_t sW = (size_t)Em*Dm, sC = (size_t)Tt*Em;
    gemm_tb(0,1, gx,wqt,bq,gq, Tt,Em,Dm, Dm,Dm,Em, Hh,1, 0,0, sW,0, sC,0, Em,0, 1.f);
    gemm_tb(0,1, gx,wkt,bk,gk, Tt,Em,Dm, Dm,Dm,Em, Hh,1, 0,0, sW,0, sC,0, Em,0, 1.f);
    gemm_tb(0,1, gx,wvt,bv,gv, Tt,Em,Dm, Dm,Dm,Em, Hh,1, 0,0, sW,0, sC,0, Em,0, 1.f);

    // transpose V per head: [H][T][E] -> [H][E][T]
    transpose_round_kernel<<<dim3(Em/32, Tt/32, Hh), tb>>>(gv, gvT, Tt, Em);

    // 3) scores = Q K^T / sqrt(S): z = b*H + h
    size_t qO = (size_t)Ss*Em, qI = (size_t)Tt*Em;
    gemm_tb(0,0, gq,gk,nullptr,gsc, Ss,Ss,Em, Em,Em,Ss, Bb*Hh,Hh,
            qO,qI, qO,qI, (size_t)Hh*Ss*Ss,(size_t)Ss*Ss, 0,0,
            0.04419417382415922f);

    // 4) softmax (+mask), rounded
    attn_softmax_kernel<<<Bb*Hh*Ss,128>>>(gsc, mask);

    // 5) ctx = attn @ V: B = Vt [H][E][T] (TB)
    gemm_tb(0,1, gsc,gvT,nullptr,gctx, Ss,Em,Ss, Ss,Tt,Hh*Em, Bb*Hh,Hh,
            (size_t)Hh*Ss*Ss,(size_t)Ss*Ss, (size_t)Ss,(size_t)Em*Tt,
            (size_t)Ss*Hh*Em,(size_t)Em, 0,0, 1.f);

    // 6) attn output proj + LN
    gemm_tb(0,0, gctx,wot,bo,gt1, Tt,Dm,Hh*Em, Hh*Em,Hh*Em,Dm, 1,1,
            0,0, 0,0, 0,0, 0,0, 1.f);
    ln_kernel<<<Tt,256>>>(gt1, lng_a, lnb_a, gt2);

    // 7) FFN
    gemm_tb(1,1, gt2,w1t,b1,gt1, Tt,Em,Dm, Dm,Dm,Em, 1,1, 0,0,0,0,0,0,0,0, 1.f);
    gemm_tb(0,0, gt1,w2t,b2,gx,  Tt,Dm,Em, Em,Em,Dm, 1,1, 0,0,0,0,0,0,0,0, 1.f);
    ln_kernel<<<Tt,256>>>(gx, lng_f, lnb_f, genc);

    // 8) vocab logits -> d_out, then log-softmax in place
    gemm_tb(0,0, genc,wpt,bp,out, Tt,Vv,Dm, Dm,Dm,Vv, 1,1, 0,0,0,0,0,0,0,0, 1.f);
    logsoftmax_kernel<<<Tt,512>>>(out);

    // 9) cls head
    cls_kernel<<<8,128>>>(genc, Wc, bc, out);
}